// round 10
// baseline (speedup 1.0000x reference)
#include <cuda_runtime.h>
#include <cuda_fp16.h>
#include <math.h>

// Problem constants
#define NB    8
#define C     528
#define T     16
#define HH    32
#define WW    32
#define R     1024
#define OUTB  8
#define SR    2
#define SCALE (1.0f/16.0f)

#define NJ    128            // layer-1 width
#define MAXSUP 144

typedef unsigned long long ull;

// projected features fp16: [pixel(b,y,x)][j]  (8192 x 128)
__device__ __half g_proj[NB * HH * WW * NJ];

// ---------------------------------------------------------------------------
// packed f32x2 helpers (FFMA2 — 2x fp32 FMA rate, full fp32 precision)
// ---------------------------------------------------------------------------
__device__ __forceinline__ ull fma2(ull a, ull b, ull c) {
    ull d;
    asm("fma.rn.f32x2 %0, %1, %2, %3;" : "=l"(d) : "l"(a), "l"(b), "l"(c));
    return d;
}
__device__ __forceinline__ ull pack_dup(float v) {
    ull d;
    asm("mov.b64 %0, {%1, %1};" : "=l"(d) : "r"(__float_as_uint(v)));
    return d;
}
__device__ __forceinline__ ull pack_pair(float lo, float hi) {
    ull d;
    asm("mov.b64 %0, {%1, %2};" : "=l"(d)
        : "r"(__float_as_uint(lo)), "r"(__float_as_uint(hi)));
    return d;
}
__device__ __forceinline__ float2 unpack2(ull v) {
    unsigned lo, hi;
    asm("mov.b64 {%0, %1}, %2;" : "=r"(lo), "=r"(hi) : "l"(v));
    return make_float2(__uint_as_float(lo), __uint_as_float(hi));
}

// ---------------------------------------------------------------------------
// Kernel 1: temporal mean + projection feat @ W1, fused.
// grid: 256 (one block per (b, y) row), block: 512.
// Thread role: xl = tid&31 (x position), cl = tid>>5 (0..15) = channel-lane
// in load phase AND j-group (8 outputs) in GEMM phase.
// Chunked over channels (16 per chunk, 33 chunks), double-buffered smem;
// GEMM accumulates with packed f32x2 FMAs hidden under the DRAM stream.
// ---------------------------------------------------------------------------
__global__ __launch_bounds__(512)
void mean_proj_kernel(const float* __restrict__ x, const float* __restrict__ W1)
{
    __shared__ float buf[2][16][32];

    const int bid = blockIdx.x;       // b*32 + y
    const int b   = bid >> 5;
    const int y   = bid & 31;
    const int tid = threadIdx.x;
    const int xl  = tid & 31;
    const int cl  = tid >> 5;         // 0..15

    ull acc0 = 0ull, acc1 = 0ull, acc2 = 0ull, acc3 = 0ull;

    const float* xb = x + ((size_t)b * C * T * HH * WW) + y * WW + xl;
    // channel stride = T*HH*WW = 16384 floats, t stride = HH*WW = 1024 floats

    // prologue: chunk 0
    {
        const float* p = xb + (size_t)cl * (T * HH * WW);
        float s0 = 0.f, s1 = 0.f;
        #pragma unroll
        for (int t = 0; t < T; t += 2) {
            s0 += __ldcs(p + t * (HH * WW));
            s1 += __ldcs(p + (t + 1) * (HH * WW));
        }
        buf[0][cl][xl] = (s0 + s1) * (1.0f / T);
    }
    __syncthreads();

    for (int ci = 1; ci <= 32; ci++) {
        // issue loads for chunk ci (hide under GEMM below)
        const float* p = xb + (size_t)(ci * 16 + cl) * (T * HH * WW);
        float s0 = 0.f, s1 = 0.f;
        #pragma unroll
        for (int t = 0; t < T; t += 2) {
            s0 += __ldcs(p + t * (HH * WW));
            s1 += __ldcs(p + (t + 1) * (HH * WW));
        }
        const float v = (s0 + s1) * (1.0f / T);

        // GEMM on chunk ci-1
        const int pb = (ci - 1) & 1;
        const int c0 = (ci - 1) * 16;
        #pragma unroll
        for (int k = 0; k < 16; k++) {
            const float4* wp = (const float4*)(W1 + (size_t)(c0 + k) * NJ + cl * 8);
            const float4 wa = wp[0];
            const float4 wb = wp[1];
            const ull pp = pack_dup(buf[pb][k][xl]);
            acc0 = fma2(pp, pack_pair(wa.x, wa.y), acc0);
            acc1 = fma2(pp, pack_pair(wa.z, wa.w), acc1);
            acc2 = fma2(pp, pack_pair(wb.x, wb.y), acc2);
            acc3 = fma2(pp, pack_pair(wb.z, wb.w), acc3);
        }

        // publish chunk ci (opposite parity from the buffer GEMM just read)
        buf[ci & 1][cl][xl] = v;
        __syncthreads();
    }

    // final GEMM: chunk 32 lives in buf[0]
    {
        const int c0 = 32 * 16;
        #pragma unroll
        for (int k = 0; k < 16; k++) {
            const float4* wp = (const float4*)(W1 + (size_t)(c0 + k) * NJ + cl * 8);
            const float4 wa = wp[0];
            const float4 wb = wp[1];
            const ull pp = pack_dup(buf[0][k][xl]);
            acc0 = fma2(pp, pack_pair(wa.x, wa.y), acc0);
            acc1 = fma2(pp, pack_pair(wa.z, wa.w), acc1);
            acc2 = fma2(pp, pack_pair(wb.x, wb.y), acc2);
            acc3 = fma2(pp, pack_pair(wb.z, wb.w), acc3);
        }
    }

    // store 8 j's as fp16 (one uint4 = 8 halves), pixel px = bid*32 + xl
    {
        const float2 f0 = unpack2(acc0);
        const float2 f1 = unpack2(acc1);
        const float2 f2 = unpack2(acc2);
        const float2 f3 = unpack2(acc3);
        __half2 h0 = __floats2half2_rn(f0.x, f0.y);
        __half2 h1 = __floats2half2_rn(f1.x, f1.y);
        __half2 h2 = __floats2half2_rn(f2.x, f2.y);
        __half2 h3 = __floats2half2_rn(f3.x, f3.y);
        uint4 st;
        st.x = *(unsigned*)&h0;
        st.y = *(unsigned*)&h1;
        st.z = *(unsigned*)&h2;
        st.w = *(unsigned*)&h3;
        const int px = bid * 32 + xl;
        ((uint4*)g_proj)[px * (NJ / 8) + cl] = st;
    }
}

// ---------------------------------------------------------------------------
// Kernel 2: ROI pooling in projected 128-dim space + bias/relu + layers 2,3.
// grid: R (one roi per block), block: 128.
// ---------------------------------------------------------------------------
__global__ __launch_bounds__(128)
void roi_head_kernel(const float* __restrict__ bbox,
                     const float* __restrict__ b1,
                     const float* __restrict__ W2, const float* __restrict__ b2,
                     const float* __restrict__ W3, const float* __restrict__ b3,
                     float* __restrict__ out)
{
    __shared__ float sAx[32], sAy[32];
    __shared__ int   sB, sXlo, sNx, sYlo, sNy, sN;
    __shared__ int   sOff[MAXSUP];     // pixel*NJ element offsets
    __shared__ float sW[MAXSUP];
    __shared__ float sH1[NJ];
    __shared__ float sPart[4][32];
    __shared__ float sH2[32];

    const int tid = threadIdx.x;
    const int roi = blockIdx.x;

    // Phase A1: per-bin axis weights, deterministic (warp0 = x, warp1 = y)
    if (tid < 64) {
        const int axis = tid >> 5;
        const int bin  = tid & 31;
        const float* bb = bbox + roi * 5;
        if (tid == 0) sB = (int)bb[0];

        const float lo_c = bb[1 + axis] * SCALE - 0.5f;
        const float hi_c = bb[3 + axis] * SCALE - 0.5f;
        const float step = (hi_c - lo_c) * (1.0f / (OUTB * SR));

        float w = 0.f;
        #pragma unroll
        for (int s = 0; s < 16; s++) {
            const float v = lo_c + ((float)s + 0.5f) * step;
            const bool valid = (v >= -1.0f) && (v <= 32.0f);
            float vc   = fminf(fmaxf(v, 0.0f), 31.0f);
            float lof  = floorf(vc);
            float frac = vc - lof;
            int ilo = (int)lof;
            int ihi = min(ilo + 1, 31);
            if (valid) {
                if (ilo == bin) w += 1.0f - frac;
                if (ihi == bin) w += frac;
            }
        }
        if (axis) sAy[bin] = w; else sAx[bin] = w;

        unsigned m = __ballot_sync(0xFFFFFFFF, w != 0.f);
        if (bin == 0) {
            int lo, n;
            if (m == 0u) { lo = 0; n = 0; }
            else { lo = __ffs(m) - 1; n = (31 - __clz(m)) - lo + 1; }
            if (axis) { sYlo = lo; sNy = n; }
            else      { sXlo = lo; sNx = n; }
        }
    }
    __syncthreads();

    // Phase A2: flatten support into (offset, weight) list
    {
        const int nx = sNx, ny = sNy;
        int n = nx * ny;
        if (n > MAXSUP) n = MAXSUP;
        if (tid == 0) sN = n;
        const int pxbase = sB * (HH * WW);
        for (int i = tid; i < n; i += 128) {
            const int iy = i / nx;
            const int ix = i - iy * nx;
            const int y  = sYlo + iy;
            const int xp = sXlo + ix;
            sOff[i] = (pxbase + y * WW + xp) * NJ;
            sW[i]   = sAy[y] * sAx[xp] * (1.0f / 256.0f);
        }
    }
    __syncthreads();

    // Phase B: gather in projected space; h1 = relu(pooled_proj + b1)
    {
        const int n = sN;
        const int j = tid;
        float acc = 0.f;
        #pragma unroll 4
        for (int i = 0; i < n; i++)
            acc = fmaf(sW[i], __half2float(g_proj[sOff[i] + j]), acc);
        sH1[j] = fmaxf(acc + b1[j], 0.f);
    }
    __syncthreads();

    // Layer 2: 128 threads = 4 k-parts x 32 outputs
    {
        const int part = tid >> 5;
        const int j2   = tid & 31;
        const int k0 = part * 32;
        float a0 = 0.f, a1 = 0.f;
        #pragma unroll
        for (int k = k0; k < k0 + 32; k += 2) {
            a0 = fmaf(sH1[k],     W2[(k)     * 32 + j2], a0);
            a1 = fmaf(sH1[k + 1], W2[(k + 1) * 32 + j2], a1);
        }
        sPart[part][j2] = a0 + a1;
    }
    __syncthreads();
    if (tid < 32) {
        sH2[tid] = (sPart[0][tid] + sPart[1][tid])
                 + (sPart[2][tid] + sPart[3][tid]) + b2[tid];
    }
    __syncthreads();

    // Layer 3 + sigmoid
    if (tid < 32) {
        float v = sH2[tid] * W3[tid];
        #pragma unroll
        for (int off = 16; off > 0; off >>= 1)
            v += __shfl_xor_sync(0xFFFFFFFF, v, off);
        if (tid == 0)
            out[roi] = 1.0f / (1.0f + expf(-(v + b3[0])));
    }
}

// ---------------------------------------------------------------------------
extern "C" void kernel_launch(void* const* d_in, const int* in_sizes, int n_in,
                              void* d_out, int out_size)
{
    const float* x    = (const float*)d_in[0];
    const float* bbox = (const float*)d_in[1];
    const float* W1   = (const float*)d_in[2];
    const float* b1   = (const float*)d_in[3];
    const float* W2   = (const float*)d_in[4];
    const float* b2   = (const float*)d_in[5];
    const float* W3   = (const float*)d_in[6];
    const float* b3   = (const float*)d_in[7];
    float* out = (float*)d_out;

    mean_proj_kernel<<<NB * HH, 512>>>(x, W1);

    roi_head_kernel<<<R, 128>>>(bbox, b1, W2, b2, W3, b3, out);
}

// round 11
// speedup vs baseline: 2.3584x; 2.3584x over previous
#include <cuda_runtime.h>
#include <cuda_fp16.h>
#include <math.h>

// Problem constants
#define NB    8
#define C     528
#define CV4   (C/4)          // 132 uint2 groups (4 fp16 channels each)
#define T     16
#define HH    32
#define WW    32
#define R     1024
#define OUTB  8
#define SR    2
#define SCALE (1.0f/16.0f)

#define MAXSUP 144

// NHWC feature scratch in fp16: [b][y][x][c]
__device__ __half g_feat_h[NB * HH * WW * C];
// pooled scratch fp32: [roi][c]
__device__ float g_pooled[R * C];

// ---------------------------------------------------------------------------
// Kernel 1: temporal mean + NCHW -> NHWC transpose, float4 loads.
// grid: (NB*HH, 17), block: 256.
// Load phase: tid = (cl<<3)|xq : channel-lane cl 0..31, x-quad xq 0..7.
//   Each thread: 16 x LDG.128 (t loop), fp32 accumulate.
// Store phase: tid = (xw<<5)|cw : 4 passes over x, 32 consecutive c per warp.
// ---------------------------------------------------------------------------
__global__ __launch_bounds__(256)
void mean_t_transpose_kernel(const float* __restrict__ x)
{
    __shared__ float tile[32][37];     // [channel][x], stride 37 conflict-free

    const int bid = blockIdx.x;        // b*32 + y
    const int b   = bid >> 5;
    const int y   = bid & 31;
    const int cchunk = blockIdx.y;

    const int tid = threadIdx.x;
    const int xq  = tid & 7;           // x/4 group
    const int cl  = tid >> 3;          // 0..31 channel lane

    const int c = cchunk * 32 + cl;
    if (c < C) {
        const float4* p = (const float4*)
            (x + (((size_t)(b * C + c) * T) * HH + y) * WW + xq * 4);
        float4 s0 = make_float4(0.f, 0.f, 0.f, 0.f);
        float4 s1 = make_float4(0.f, 0.f, 0.f, 0.f);
        #pragma unroll
        for (int t = 0; t < T; t += 2) {
            const float4 v0 = __ldcs(p + (size_t)t       * (HH * WW / 4));
            const float4 v1 = __ldcs(p + (size_t)(t + 1) * (HH * WW / 4));
            s0.x += v0.x; s0.y += v0.y; s0.z += v0.z; s0.w += v0.w;
            s1.x += v1.x; s1.y += v1.y; s1.z += v1.z; s1.w += v1.w;
        }
        const int xb = xq * 4;
        tile[cl][xb + 0] = (s0.x + s1.x) * (1.0f / T);
        tile[cl][xb + 1] = (s0.y + s1.y) * (1.0f / T);
        tile[cl][xb + 2] = (s0.z + s1.z) * (1.0f / T);
        tile[cl][xb + 3] = (s0.w + s1.w) * (1.0f / T);
    }
    __syncthreads();

    const int cw = tid & 31;           // channel within chunk
    const int xw = tid >> 5;           // 0..7
    const int c2 = cchunk * 32 + cw;
    if (c2 < C) {
        #pragma unroll
        for (int xs = 0; xs < 4; xs++) {
            const int xx = xs * 8 + xw;
            g_feat_h[(((size_t)(b * HH + y)) * WW + xx) * C + c2] =
                __float2half(tile[cw][xx]);
        }
    }
}

// ---------------------------------------------------------------------------
// Kernel 2: ROI pooling, flattened support list, 4 independent acc streams.
// grid: R, block: 160 (132 active in gather).
// ---------------------------------------------------------------------------
__global__ __launch_bounds__(160)
void roi_pool_kernel(const float* __restrict__ bbox)
{
    __shared__ float sAx[32], sAy[32];
    __shared__ int   sB, sXlo, sNx, sYlo, sNy, sN;
    __shared__ int   sOff[MAXSUP];     // pixel offset in uint2 units
    __shared__ float sW[MAXSUP];

    const int tid = threadIdx.x;
    const int roi = blockIdx.x;

    // Phase A1: per-bin axis weights (warp0 = x, warp1 = y), deterministic
    if (tid < 64) {
        const int axis = tid >> 5;
        const int bin  = tid & 31;
        const float* bb = bbox + roi * 5;
        if (tid == 0) sB = (int)bb[0];

        const float lo_c = bb[1 + axis] * SCALE - 0.5f;
        const float hi_c = bb[3 + axis] * SCALE - 0.5f;
        const float step = (hi_c - lo_c) * (1.0f / (OUTB * SR));

        float w = 0.f;
        #pragma unroll
        for (int s = 0; s < 16; s++) {
            const float v = lo_c + ((float)s + 0.5f) * step;
            const bool valid = (v >= -1.0f) && (v <= 32.0f);
            float vc   = fminf(fmaxf(v, 0.0f), 31.0f);
            float lof  = floorf(vc);
            float frac = vc - lof;
            int ilo = (int)lof;
            int ihi = min(ilo + 1, 31);
            if (valid) {
                if (ilo == bin) w += 1.0f - frac;
                if (ihi == bin) w += frac;
            }
        }
        if (axis) sAy[bin] = w; else sAx[bin] = w;

        unsigned m = __ballot_sync(0xFFFFFFFF, w != 0.f);
        if (bin == 0) {
            int lo, n;
            if (m == 0u) { lo = 0; n = 0; }
            else { lo = __ffs(m) - 1; n = (31 - __clz(m)) - lo + 1; }
            if (axis) { sYlo = lo; sNy = n; }
            else      { sXlo = lo; sNx = n; }
        }
    }
    __syncthreads();

    // Phase A2: flatten support into (offset, weight) list
    {
        const int nx = sNx, ny = sNy;
        int n = nx * ny;
        if (n > MAXSUP) n = MAXSUP;
        if (tid == 0) sN = n;
        for (int i = tid; i < n; i += 160) {
            const int iy = i / nx;
            const int ix = i - iy * nx;
            const int y  = sYlo + iy;
            const int xp = sXlo + ix;
            sOff[i] = (y * WW + xp) * CV4;
            sW[i]   = sAy[y] * sAx[xp] * (1.0f / 256.0f);
        }
    }
    __syncthreads();

    // Phase B: flat gather, 4 independent accumulator streams
    if (tid < CV4) {
        const int n = sN;
        const uint2* base = (const uint2*)g_feat_h
                          + (size_t)sB * (HH * WW * CV4) + tid;

        float4 A0 = make_float4(0.f, 0.f, 0.f, 0.f);
        float4 A1 = make_float4(0.f, 0.f, 0.f, 0.f);
        float4 A2 = make_float4(0.f, 0.f, 0.f, 0.f);
        float4 A3 = make_float4(0.f, 0.f, 0.f, 0.f);

        int i = 0;
        for (; i + 4 <= n; i += 4) {
            const uint2 r0 = base[sOff[i + 0]];
            const uint2 r1 = base[sOff[i + 1]];
            const uint2 r2 = base[sOff[i + 2]];
            const uint2 r3 = base[sOff[i + 3]];
            const float w0 = sW[i + 0], w1 = sW[i + 1];
            const float w2 = sW[i + 2], w3 = sW[i + 3];

            float2 a, b2;
            a  = __half22float2(*(const __half2*)&r0.x);
            b2 = __half22float2(*(const __half2*)&r0.y);
            A0.x = fmaf(w0, a.x,  A0.x); A0.y = fmaf(w0, a.y,  A0.y);
            A0.z = fmaf(w0, b2.x, A0.z); A0.w = fmaf(w0, b2.y, A0.w);

            a  = __half22float2(*(const __half2*)&r1.x);
            b2 = __half22float2(*(const __half2*)&r1.y);
            A1.x = fmaf(w1, a.x,  A1.x); A1.y = fmaf(w1, a.y,  A1.y);
            A1.z = fmaf(w1, b2.x, A1.z); A1.w = fmaf(w1, b2.y, A1.w);

            a  = __half22float2(*(const __half2*)&r2.x);
            b2 = __half22float2(*(const __half2*)&r2.y);
            A2.x = fmaf(w2, a.x,  A2.x); A2.y = fmaf(w2, a.y,  A2.y);
            A2.z = fmaf(w2, b2.x, A2.z); A2.w = fmaf(w2, b2.y, A2.w);

            a  = __half22float2(*(const __half2*)&r3.x);
            b2 = __half22float2(*(const __half2*)&r3.y);
            A3.x = fmaf(w3, a.x,  A3.x); A3.y = fmaf(w3, a.y,  A3.y);
            A3.z = fmaf(w3, b2.x, A3.z); A3.w = fmaf(w3, b2.y, A3.w);
        }
        for (; i < n; i++) {
            const uint2 raw = base[sOff[i]];
            const float w = sW[i];
            const float2 a  = __half22float2(*(const __half2*)&raw.x);
            const float2 b2 = __half22float2(*(const __half2*)&raw.y);
            A0.x = fmaf(w, a.x,  A0.x); A0.y = fmaf(w, a.y,  A0.y);
            A0.z = fmaf(w, b2.x, A0.z); A0.w = fmaf(w, b2.y, A0.w);
        }

        float4 acc;
        acc.x = (A0.x + A1.x) + (A2.x + A3.x);
        acc.y = (A0.y + A1.y) + (A2.y + A3.y);
        acc.z = (A0.z + A1.z) + (A2.z + A3.z);
        acc.w = (A0.w + A1.w) + (A2.w + A3.w);
        ((float4*)g_pooled)[(size_t)roi * CV4 + tid] = acc;
    }
}

// ---------------------------------------------------------------------------
// Kernel 3: MLP 528 -> 128 (relu) -> 32 -> 1 (sigmoid), 8 rois per block.
// grid: R/8 = 128, block: 256. Layer 1 register-tiled GEMM.
// ---------------------------------------------------------------------------
#define MR 8

__global__ __launch_bounds__(256)
void mlp_kernel(const float* __restrict__ W1, const float* __restrict__ b1,
                const float* __restrict__ W2, const float* __restrict__ b2,
                const float* __restrict__ W3, const float* __restrict__ b3,
                float* __restrict__ out)
{
    __shared__ float sPooled[MR][C];
    __shared__ float sH1[MR][128];
    __shared__ float sH2[MR][32];

    const int tid  = threadIdx.x;
    const int roi0 = blockIdx.x * MR;

    {
        const float4* gp4 = (const float4*)g_pooled + (size_t)roi0 * CV4;
        float4* sp4 = (float4*)&sPooled[0][0];
        #pragma unroll
        for (int u = tid; u < MR * CV4; u += 256)
            sp4[u] = gp4[u];
    }
    __syncthreads();

    // Layer 1
    {
        const int lane = tid & 31;
        const int w    = tid >> 5;            // warp 0..7
        const int part = lane >> 2;           // 0..7 (c-part, 66 each)
        const int jq   = lane & 3;
        const int j4   = w * 4 + jq;          // float4 index over j (0..31)
        const int c0   = part * 66;

        const float4* W1_4 = (const float4*)W1;   // [c][32]

        float4 a[MR];
        #pragma unroll
        for (int r = 0; r < MR; r++) a[r] = make_float4(0.f, 0.f, 0.f, 0.f);

        #pragma unroll 2
        for (int c = c0; c < c0 + 66; c++) {
            const float4 wv = W1_4[c * 32 + j4];
            #pragma unroll
            for (int r = 0; r < MR; r++) {
                const float p = sPooled[r][c];
                a[r].x = fmaf(p, wv.x, a[r].x);
                a[r].y = fmaf(p, wv.y, a[r].y);
                a[r].z = fmaf(p, wv.z, a[r].z);
                a[r].w = fmaf(p, wv.w, a[r].w);
            }
        }

        #pragma unroll
        for (int off = 4; off <= 16; off <<= 1) {
            #pragma unroll
            for (int r = 0; r < MR; r++) {
                a[r].x += __shfl_xor_sync(0xFFFFFFFF, a[r].x, off);
                a[r].y += __shfl_xor_sync(0xFFFFFFFF, a[r].y, off);
                a[r].z += __shfl_xor_sync(0xFFFFFFFF, a[r].z, off);
                a[r].w += __shfl_xor_sync(0xFFFFFFFF, a[r].w, off);
            }
        }

        if (part == 0) {
            const float4 bb = ((const float4*)b1)[j4];
            #pragma unroll
            for (int r = 0; r < MR; r++) {
                float4 h;
                h.x = fmaxf(a[r].x + bb.x, 0.f);
                h.y = fmaxf(a[r].y + bb.y, 0.f);
                h.z = fmaxf(a[r].z + bb.z, 0.f);
                h.w = fmaxf(a[r].w + bb.w, 0.f);
                ((float4*)&sH1[r][0])[j4] = h;
            }
        }
    }
    __syncthreads();

    // Layer 2
    {
        const int r = tid >> 5;
        const int j = tid & 31;
        const float* h = sH1[r];
        float a0 = 0.f, a1 = 0.f;
        #pragma unroll
        for (int k = 0; k < 128; k += 2) {
            a0 = fmaf(h[k],     W2[(k)     * 32 + j], a0);
            a1 = fmaf(h[k + 1], W2[(k + 1) * 32 + j], a1);
        }
        sH2[r][j] = a0 + a1 + b2[j];
    }
    __syncthreads();

    // Layer 3 + sigmoid
    {
        const int r    = tid >> 5;
        const int lane = tid & 31;
        float v = sH2[r][lane] * W3[lane];
        #pragma unroll
        for (int off = 16; off > 0; off >>= 1)
            v += __shfl_xor_sync(0xFFFFFFFF, v, off);
        if (lane == 0)
            out[roi0 + r] = 1.0f / (1.0f + expf(-(v + b3[0])));
    }
}

// ---------------------------------------------------------------------------
extern "C" void kernel_launch(void* const* d_in, const int* in_sizes, int n_in,
                              void* d_out, int out_size)
{
    const float* x    = (const float*)d_in[0];
    const float* bbox = (const float*)d_in[1];
    const float* W1   = (const float*)d_in[2];
    const float* b1   = (const float*)d_in[3];
    const float* W2   = (const float*)d_in[4];
    const float* b2   = (const float*)d_in[5];
    const float* W3   = (const float*)d_in[6];
    const float* b3   = (const float*)d_in[7];
    float* out = (float*)d_out;

    dim3 g1(NB * HH, 17);
    mean_t_transpose_kernel<<<g1, 256>>>(x);

    roi_pool_kernel<<<R, 160>>>(bbox);

    mlp_kernel<<<R / MR, 256>>>(W1, b1, W2, b2, W3, b3, out);
}